// round 4
// baseline (speedup 1.0000x reference)
#include <cuda_runtime.h>

#define MTOT 8192
#define LW   64      // ww
#define RW   100     // WP*WP
#define CD   128
#define CF   120     // C - SLICE

typedef unsigned long long ull;

__device__ __forceinline__ ull pack2(float x, float y) {
    ull r; asm("mov.b64 %0, {%1,%2};" : "=l"(r) : "f"(x), "f"(y)); return r;
}
__device__ __forceinline__ float2 unpack2(ull p) {
    float2 f; asm("mov.b64 {%0,%1}, %2;" : "=f"(f.x), "=f"(f.y) : "l"(p)); return f;
}
__device__ __forceinline__ void ffma2(ull& d, ull a, ull b) {
    asm("fma.rn.f32x2 %0, %1, %2, %0;" : "+l"(d) : "l"(a), "l"(b));
}

// ---- shared memory layout (floats) ----
// f1sT : 128c x (stride 106, EVEN for LDS.64 alignment) transposed, scales folded
//        [0, 13568). conf (64 x 102 = 6528) aliases [0, 6528) after mainloop;
//        ff channels (c>=120) live at >=12720 — disjoint from conf.
#define F1STR    106
#define OFF_F1   0
#define OFF_CONF 0
#define CSTR     102
#define OFF_RMAX 13568
#define OFF_RINV 13632
#define OFF_CMAX 13696
#define OFF_CINV 13808
#define OFF_REDV 13920
#define OFF_REDI 13936
#define SMEM_FLOATS 13952
#define SMEM_BYTES (SMEM_FLOATS * 4)

__global__ void __launch_bounds__(256, 3)
fine_matching_kernel(const float* __restrict__ feat0,
                     const float* __restrict__ feat1,
                     const float* __restrict__ mk0,
                     const float* __restrict__ mk1,
                     float* __restrict__ out)
{
    extern __shared__ float smem[];
    float* f1sT = smem + OFF_F1;
    float* conf = smem + OFF_CONF;
    float* rmax = smem + OFF_RMAX;
    float* rinv = smem + OFF_RINV;
    float* cmax = smem + OFF_CMAX;
    float* cinv = smem + OFF_CINV;
    float* redv = smem + OFF_REDV;
    int*   redi = (int*)(smem + OFF_REDI);

    const int m    = blockIdx.x;
    const int tid  = threadIdx.x;
    const int warp = tid >> 5;
    const int lane = tid & 31;

    // ---- stage feat1 row: transpose + fold scales (stride 106) ----
    const float4* g1 = (const float4*)(feat1 + (size_t)m * (RW * CD));
    for (int i4 = tid; i4 < (RW * CD) / 4; i4 += 256) {
        float4 v  = g1[i4];
        int  flat = i4 * 4;
        int  r    = flat >> 7;
        int  c0   = flat & 127;
        float s   = (c0 < CF) ? (1.0f / 128.0f) : 0.35355339059327373f;
        f1sT[(c0 + 0) * F1STR + r] = v.x * s;
        f1sT[(c0 + 1) * F1STR + r] = v.y * s;
        f1sT[(c0 + 2) * F1STR + r] = v.z * s;
        f1sT[(c0 + 3) * F1STR + r] = v.w * s;
    }
    __syncthreads();

    // ---- mainloop: warp tile = 8 l x (64+36) r; a from global (broadcast LDG) ----
    const int l0 = warp * 8;
    const int r0 = 2 * lane;
    const float* f0p = feat0 + (size_t)m * (LW * CD) + l0 * CD;
    ull acc[8][2];
    #pragma unroll
    for (int j = 0; j < 8; ++j) { acc[j][0] = 0ull; acc[j][1] = 0ull; }

    for (int c4 = 0; c4 < CF; c4 += 4) {
        float4 a4[8];
        #pragma unroll
        for (int j = 0; j < 8; ++j)
            a4[j] = __ldg((const float4*)(f0p + j * CD + c4));
        #pragma unroll
        for (int i = 0; i < 4; ++i) {
            const float* f1c = &f1sT[(c4 + i) * F1STR];
            ull b0 = *(const ull*)(f1c + r0);
            ull b1 = *(const ull*)(f1c + 64 + r0);
            #pragma unroll
            for (int j = 0; j < 8; ++j) {
                float a = (i == 0) ? a4[j].x : (i == 1) ? a4[j].y
                         : (i == 2) ? a4[j].z : a4[j].w;
                ull aa = pack2(a, a);
                ffma2(acc[j][0], aa, b0);
                ffma2(acc[j][1], aa, b1);
            }
        }
    }
    __syncthreads();   // all f1sT (c<120) reads done; conf may alias it

    // store conf from registers (r >= 100 lanes hold garbage; never stored)
    #pragma unroll
    for (int j = 0; j < 8; ++j) {
        float2 p0 = unpack2(acc[j][0]);
        *(float2*)&conf[(l0 + j) * CSTR + r0] = p0;
        if (lane < 18) {
            float2 p1 = unpack2(acc[j][1]);
            *(float2*)&conf[(l0 + j) * CSTR + 64 + r0] = p1;
        }
    }
    __syncthreads();

    // ---- softmax stats, split across warps ----
    if (warp < 4) {
        // row stats (axis=2 over 100 r): warps 0-3, 16 rows each
        #pragma unroll 4
        for (int q = 0; q < 16; ++q) {
            int l = warp * 16 + q;
            const float* row = &conf[l * CSTR];
            float v0 = row[lane], v1 = row[lane + 32], v2 = row[lane + 64];
            float v3 = (lane < 4) ? row[lane + 96] : -1e30f;
            float mx = fmaxf(fmaxf(v0, v1), fmaxf(v2, v3));
            #pragma unroll
            for (int o = 16; o; o >>= 1) mx = fmaxf(mx, __shfl_xor_sync(~0u, mx, o));
            float s = __expf(v0 - mx) + __expf(v1 - mx) + __expf(v2 - mx)
                    + __expf(v3 - mx);   // exp(-huge)=0 for lane>=4
            #pragma unroll
            for (int o = 16; o; o >>= 1) s += __shfl_xor_sync(~0u, s, o);
            if (lane == 0) { rmax[l] = mx; rinv[l] = 1.f / s; }
        }
    } else {
        // col stats (axis=1 over 64 l): warps 4-7, one column per thread
        int r = (warp - 4) * 32 + lane;
        if (r < RW) {
            float m0 = -1e30f, m1 = -1e30f, m2 = -1e30f, m3 = -1e30f;
            #pragma unroll
            for (int l = 0; l < LW; l += 4) {
                m0 = fmaxf(m0, conf[(l + 0) * CSTR + r]);
                m1 = fmaxf(m1, conf[(l + 1) * CSTR + r]);
                m2 = fmaxf(m2, conf[(l + 2) * CSTR + r]);
                m3 = fmaxf(m3, conf[(l + 3) * CSTR + r]);
            }
            float mx = fmaxf(fmaxf(m0, m1), fmaxf(m2, m3));
            float s0 = 0.f, s1 = 0.f, s2 = 0.f, s3 = 0.f;
            #pragma unroll
            for (int l = 0; l < LW; l += 4) {
                s0 += __expf(conf[(l + 0) * CSTR + r] - mx);
                s1 += __expf(conf[(l + 1) * CSTR + r] - mx);
                s2 += __expf(conf[(l + 2) * CSTR + r] - mx);
                s3 += __expf(conf[(l + 3) * CSTR + r] - mx);
            }
            cmax[r] = mx; cinv[r] = 1.f / ((s0 + s1) + (s2 + s3));
        }
    }
    __syncthreads();

    // ---- cropped sm write + argmax (first-occurrence tie-break) ----
    const int rc = tid & 63;
    const int r  = (rc >> 3) * 10 + (rc & 7) + 11;
    const float cm = cmax[r], ci = cinv[r];
    const int lb = tid >> 6;
    float bv = -1e30f; int bi = 0;
    float* outm = out + (size_t)m * 4096;
    #pragma unroll
    for (int e8 = 0; e8 < 16; ++e8) {
        int l = e8 * 4 + lb;
        float v = conf[l * CSTR + r];
        float s = __expf(2.f * v - rmax[l] - cm) * rinv[l] * ci;
        int flat = l * 64 + rc;
        outm[flat] = s;
        if (s > bv) { bv = s; bi = flat; }   // ascending flat per thread
    }
    #pragma unroll
    for (int o = 16; o; o >>= 1) {
        float v2 = __shfl_xor_sync(~0u, bv, o);
        int   i2 = __shfl_xor_sync(~0u, bi, o);
        if (v2 > bv || (v2 == bv && i2 < bi)) { bv = v2; bi = i2; }
    }
    if (lane == 0) { redv[warp] = bv; redi[warp] = bi; }
    __syncthreads();

    // ---- warp 0: final reduce + epilogue ----
    if (warp == 0) {
        float v = (lane < 8) ? redv[lane] : -1e30f;
        int   i = (lane < 8) ? redi[lane] : 0x7fffffff;
        #pragma unroll
        for (int o = 4; o; o >>= 1) {
            float v2 = __shfl_xor_sync(~0u, v, o);
            int   i2 = __shfl_xor_sync(~0u, i, o);
            if (v2 > v || (v2 == v && i2 < i)) { v = v2; i = i2; }
        }
        if (lane == 0) {
            int idx = i;
            int il = idx >> 6, ir = idx & 63;
            float dlx = (float)(il & 7) - 3.5f, dly = (float)(il >> 3) - 3.5f;
            float drx = (float)(ir & 7) - 3.5f, dry = (float)(ir >> 3) - 3.5f;

            // last 8 channels of f0 row il, straight from global (L2-hot)
            float4 av0 = __ldg((const float4*)(feat0 + (size_t)m * (LW * CD) + il * CD + CF));
            float4 av1 = __ldg((const float4*)(feat0 + (size_t)m * (LW * CD) + il * CD + CF + 4));
            float av[8] = {av0.x, av0.y, av0.z, av0.w, av1.x, av1.y, av1.z, av1.w};

            float p[9];
            int ib = ir >> 3, jb = ir & 7;
            #pragma unroll
            for (int di = 0; di < 3; ++di) {
                int ii = ib + di - 1; ii = (ii < 0) ? ii + 10 : ((ii > 9) ? ii - 10 : ii);
                #pragma unroll
                for (int dj = 0; dj < 3; ++dj) {
                    int jj = jb + dj - 1; jj = (jj < 0) ? jj + 10 : ((jj > 9) ? jj - 10 : jj);
                    int rr = ii * 10 + jj;
                    float s = 0.f;
                    #pragma unroll
                    for (int t = 0; t < 8; ++t)
                        s += av[t] * f1sT[(CF + t) * F1STR + rr];
                    p[di * 3 + dj] = s;
                }
            }
            float mx = p[0];
            #pragma unroll
            for (int t = 1; t < 9; ++t) mx = fmaxf(mx, p[t]);
            float h[9], se = 0.f;
            #pragma unroll
            for (int t = 0; t < 9; ++t) { h[t] = __expf((p[t] - mx) * 0.1f); se += h[t]; }
            float inv = 1.f / se;
            float ex = 0.f, ey = 0.f;
            #pragma unroll
            for (int di = 0; di < 3; ++di)
                #pragma unroll
                for (int dj = 0; dj < 3; ++dj) {
                    ex += h[di * 3 + dj] * (float)(dj - 1);
                    ey += h[di * 3 + dj] * (float)(di - 1);
                }
            ex *= inv; ey *= inv;

            float mk0x = mk0[2 * m], mk0y = mk0[2 * m + 1];
            float mk1x = mk1[2 * m], mk1y = mk1[2 * m + 1];
            size_t base = (size_t)MTOT * 4096;
            out[base + 2 * m]     = mk0x + dlx * 2.f;
            out[base + 2 * m + 1] = mk0y + dly * 2.f;
            out[base + 2 * MTOT + 2 * m]     = mk1x + drx * 2.f + ex * 2.f;
            out[base + 2 * MTOT + 2 * m + 1] = mk1y + dry * 2.f + ey * 2.f;
        }
    }
}

extern "C" void kernel_launch(void* const* d_in, const int* in_sizes, int n_in,
                              void* d_out, int out_size)
{
    const float* feat0 = (const float*)d_in[0];
    const float* feat1 = (const float*)d_in[1];
    const float* mk0   = (const float*)d_in[2];
    const float* mk1   = (const float*)d_in[3];
    float* out = (float*)d_out;

    cudaFuncSetAttribute(fine_matching_kernel,
                         cudaFuncAttributeMaxDynamicSharedMemorySize, SMEM_BYTES);
    fine_matching_kernel<<<MTOT, 256, SMEM_BYTES>>>(feat0, feat1, mk0, mk1, out);
}

// round 6
// speedup vs baseline: 1.8125x; 1.8125x over previous
#include <cuda_runtime.h>
#include <cstdint>

#define MTOT 8192
#define LW   64      // ww
#define RW   100     // WP*WP
#define CD   128
#define CF   120     // C - SLICE

typedef unsigned long long ull;
typedef unsigned int u32;

__device__ __forceinline__ ull pack2(float x, float y) {
    ull r; asm("mov.b64 %0, {%1,%2};" : "=l"(r) : "f"(x), "f"(y)); return r;
}
__device__ __forceinline__ float2 unpack2(ull p) {
    float2 f; asm("mov.b64 {%0,%1}, %2;" : "=f"(f.x), "=f"(f.y) : "l"(p)); return f;
}
__device__ __forceinline__ void ffma2(ull& d, ull a, ull b) {
    asm("fma.rn.f32x2 %0, %1, %2, %0;" : "+l"(d) : "l"(a), "l"(b));
}
__device__ __forceinline__ void cp_async16(u32 smem_addr, const void* gptr) {
    asm volatile("cp.async.ca.shared.global [%0], [%1], 16;\n"
                 :: "r"(smem_addr), "l"(gptr) : "memory");
}
#define CP_COMMIT() asm volatile("cp.async.commit_group;\n" ::: "memory")
#define CP_WAIT(N)  asm volatile("cp.async.wait_group %0;\n" :: "n"(N) : "memory")

// ---- shared memory layout (floats) ----
// f1sT : 128c x stride 106 transposed, scales folded          [0, 13568)
//        conf (64 x 102 = 6528) aliases [0, 6528) post-mainloop;
//        ff channels (c>=120) live at >=12720 — disjoint.
// misc : [13568, 13952)
// f0c  : 2 x (64 l x 32 c) chunk double-buffer                [13952, 18048)
#define F1STR    106
#define OFF_F1   0
#define OFF_CONF 0
#define CSTR     102
#define OFF_RMAX 13568
#define OFF_RINV 13632
#define OFF_CMAX 13696
#define OFF_CINV 13808
#define OFF_REDV 13920
#define OFF_REDI 13936
#define OFF_F0C  13952
#define CHUNK_FLOATS 2048      // 64*32
#define SMEM_FLOATS (OFF_F0C + 2 * CHUNK_FLOATS)
#define SMEM_BYTES (SMEM_FLOATS * 4)

__global__ void __launch_bounds__(256, 3)
fine_matching_kernel(const float* __restrict__ feat0,
                     const float* __restrict__ feat1,
                     const float* __restrict__ mk0,
                     const float* __restrict__ mk1,
                     float* __restrict__ out)
{
    extern __shared__ float smem[];
    float* f1sT = smem + OFF_F1;
    float* conf = smem + OFF_CONF;
    float* rmax = smem + OFF_RMAX;
    float* rinv = smem + OFF_RINV;
    float* cmax = smem + OFF_CMAX;
    float* cinv = smem + OFF_CINV;
    float* redv = smem + OFF_REDV;
    int*   redi = (int*)(smem + OFF_REDI);
    float* f0c  = smem + OFF_F0C;

    const int m    = blockIdx.x;
    const int tid  = threadIdx.x;
    const int warp = tid >> 5;
    const int lane = tid & 31;

    u32 smem_u32;
    { unsigned long long gp = __cvta_generic_to_shared(smem); smem_u32 = (u32)gp; }

    const float* f0base = feat0 + (size_t)m * (LW * CD);

    // ---- stage f0 chunk (ck) into buffer (buf) via cp.async: 512 x 16B ----
    #define STAGE_F0(buf, ck) do {                                            \
        int _idx0 = tid;                                                      \
        int _l0s = _idx0 >> 3, _cc0 = (_idx0 & 7) * 4;                        \
        cp_async16(smem_u32 + (OFF_F0C + (buf) * CHUNK_FLOATS + _l0s * 32 + _cc0) * 4, \
                   f0base + _l0s * CD + (ck) * 32 + _cc0);                    \
        int _idx1 = tid + 256;                                                \
        int _l1s = _idx1 >> 3, _cc1 = (_idx1 & 7) * 4;                        \
        cp_async16(smem_u32 + (OFF_F0C + (buf) * CHUNK_FLOATS + _l1s * 32 + _cc1) * 4, \
                   f0base + _l1s * CD + (ck) * 32 + _cc1);                    \
    } while (0)

    // kick off first two chunks
    STAGE_F0(0, 0); CP_COMMIT();
    STAGE_F0(1, 1); CP_COMMIT();

    // ---- stage feat1 row: transpose + fold scales (stride 106) ----
    const float4* g1 = (const float4*)(feat1 + (size_t)m * (RW * CD));
    for (int i4 = tid; i4 < (RW * CD) / 4; i4 += 256) {
        float4 v  = g1[i4];
        int  flat = i4 * 4;
        int  r    = flat >> 7;
        int  c0   = flat & 127;
        float s   = (c0 < CF) ? (1.0f / 128.0f) : 0.35355339059327373f;
        f1sT[(c0 + 0) * F1STR + r] = v.x * s;
        f1sT[(c0 + 1) * F1STR + r] = v.y * s;
        f1sT[(c0 + 2) * F1STR + r] = v.z * s;
        f1sT[(c0 + 3) * F1STR + r] = v.w * s;
    }
    CP_WAIT(1);            // chunk 0 resident
    __syncthreads();       // f1sT + chunk0 visible to all

    // ---- mainloop: 4 chunks of 32 channels (last uses 24), double-buffered ----
    const int l0 = warp * 8;
    const int r0 = 2 * lane;
    ull acc[8][2];
    #pragma unroll
    for (int j = 0; j < 8; ++j) { acc[j][0] = 0ull; acc[j][1] = 0ull; }

    #pragma unroll
    for (int ck = 0; ck < 4; ++ck) {
        const float* fb = &f0c[(ck & 1) * CHUNK_FLOATS];
        const int cend = (ck == 3) ? 24 : 32;
        for (int cc = 0; cc < cend; cc += 4) {
            const int c4 = ck * 32 + cc;
            float4 a4[8];
            #pragma unroll
            for (int j = 0; j < 8; ++j)
                a4[j] = *(const float4*)&fb[(l0 + j) * 32 + cc];
            #pragma unroll
            for (int i = 0; i < 4; ++i) {
                const float* f1c = &f1sT[(c4 + i) * F1STR];
                ull b0 = *(const ull*)(f1c + r0);
                ull b1 = *(const ull*)(f1c + 64 + r0);
                #pragma unroll
                for (int j = 0; j < 8; ++j) {
                    float a = (i == 0) ? a4[j].x : (i == 1) ? a4[j].y
                             : (i == 2) ? a4[j].z : a4[j].w;
                    ull aa = pack2(a, a);
                    ffma2(acc[j][0], aa, b0);
                    ffma2(acc[j][1], aa, b1);
                }
            }
        }
        __syncthreads();                    // all warps done reading buf(ck&1)
        if (ck < 2) {
            STAGE_F0(ck & 1, ck + 2);       // refill freed buffer
            CP_COMMIT();
            CP_WAIT(1);                     // chunk ck+1 resident
            __syncthreads();
        } else if (ck == 2) {
            CP_WAIT(0);                     // chunk 3 resident
            __syncthreads();
        }
    }
    // conf may now alias f1sT low region (all c<120 reads done)

    // store conf from registers (r >= 100 lanes hold garbage; never stored)
    #pragma unroll
    for (int j = 0; j < 8; ++j) {
        float2 p0 = unpack2(acc[j][0]);
        *(float2*)&conf[(l0 + j) * CSTR + r0] = p0;
        if (lane < 18) {
            float2 p1 = unpack2(acc[j][1]);
            *(float2*)&conf[(l0 + j) * CSTR + 64 + r0] = p1;
        }
    }
    __syncthreads();

    // ---- softmax stats, split across warps ----
    if (warp < 4) {
        // row stats (axis=2 over 100 r): warps 0-3, 16 rows each
        #pragma unroll 4
        for (int q = 0; q < 16; ++q) {
            int l = warp * 16 + q;
            const float* row = &conf[l * CSTR];
            float v0 = row[lane], v1 = row[lane + 32], v2 = row[lane + 64];
            float v3 = (lane < 4) ? row[lane + 96] : -1e30f;
            float mx = fmaxf(fmaxf(v0, v1), fmaxf(v2, v3));
            #pragma unroll
            for (int o = 16; o; o >>= 1) mx = fmaxf(mx, __shfl_xor_sync(~0u, mx, o));
            float s = __expf(v0 - mx) + __expf(v1 - mx) + __expf(v2 - mx)
                    + __expf(v3 - mx);   // exp(-huge)=0 for lane>=4
            #pragma unroll
            for (int o = 16; o; o >>= 1) s += __shfl_xor_sync(~0u, s, o);
            if (lane == 0) { rmax[l] = mx; rinv[l] = 1.f / s; }
        }
    } else {
        // col stats (axis=1 over 64 l): warps 4-7, one column per thread
        int r = (warp - 4) * 32 + lane;
        if (r < RW) {
            float m0 = -1e30f, m1 = -1e30f, m2 = -1e30f, m3 = -1e30f;
            #pragma unroll
            for (int l = 0; l < LW; l += 4) {
                m0 = fmaxf(m0, conf[(l + 0) * CSTR + r]);
                m1 = fmaxf(m1, conf[(l + 1) * CSTR + r]);
                m2 = fmaxf(m2, conf[(l + 2) * CSTR + r]);
                m3 = fmaxf(m3, conf[(l + 3) * CSTR + r]);
            }
            float mx = fmaxf(fmaxf(m0, m1), fmaxf(m2, m3));
            float s0 = 0.f, s1 = 0.f, s2 = 0.f, s3 = 0.f;
            #pragma unroll
            for (int l = 0; l < LW; l += 4) {
                s0 += __expf(conf[(l + 0) * CSTR + r] - mx);
                s1 += __expf(conf[(l + 1) * CSTR + r] - mx);
                s2 += __expf(conf[(l + 2) * CSTR + r] - mx);
                s3 += __expf(conf[(l + 3) * CSTR + r] - mx);
            }
            cmax[r] = mx; cinv[r] = 1.f / ((s0 + s1) + (s2 + s3));
        }
    }
    __syncthreads();

    // ---- cropped sm write + argmax (first-occurrence tie-break) ----
    const int rc = tid & 63;
    const int r  = (rc >> 3) * 10 + (rc & 7) + 11;
    const float cm = cmax[r], ci = cinv[r];
    const int lb = tid >> 6;
    float bv = -1e30f; int bi = 0;
    float* outm = out + (size_t)m * 4096;
    #pragma unroll
    for (int e8 = 0; e8 < 16; ++e8) {
        int l = e8 * 4 + lb;
        float v = conf[l * CSTR + r];
        float s = __expf(2.f * v - rmax[l] - cm) * rinv[l] * ci;
        int flat = l * 64 + rc;
        outm[flat] = s;
        if (s > bv) { bv = s; bi = flat; }   // ascending flat per thread
    }
    #pragma unroll
    for (int o = 16; o; o >>= 1) {
        float v2 = __shfl_xor_sync(~0u, bv, o);
        int   i2 = __shfl_xor_sync(~0u, bi, o);
        if (v2 > bv || (v2 == bv && i2 < bi)) { bv = v2; bi = i2; }
    }
    if (lane == 0) { redv[warp] = bv; redi[warp] = bi; }
    __syncthreads();

    // ---- warp 0: final reduce + epilogue ----
    if (warp == 0) {
        float v = (lane < 8) ? redv[lane] : -1e30f;
        int   i = (lane < 8) ? redi[lane] : 0x7fffffff;
        #pragma unroll
        for (int o = 4; o; o >>= 1) {
            float v2 = __shfl_xor_sync(~0u, v, o);
            int   i2 = __shfl_xor_sync(~0u, i, o);
            if (v2 > v || (v2 == v && i2 < i)) { v = v2; i = i2; }
        }
        if (lane == 0) {
            int idx = i;
            int il = idx >> 6, ir = idx & 63;
            float dlx = (float)(il & 7) - 3.5f, dly = (float)(il >> 3) - 3.5f;
            float drx = (float)(ir & 7) - 3.5f, dry = (float)(ir >> 3) - 3.5f;

            // last 8 channels of f0 row il, straight from global (L2-hot)
            float4 av0 = __ldg((const float4*)(f0base + il * CD + CF));
            float4 av1 = __ldg((const float4*)(f0base + il * CD + CF + 4));
            float av[8] = {av0.x, av0.y, av0.z, av0.w, av1.x, av1.y, av1.z, av1.w};

            float p[9];
            int ib = ir >> 3, jb = ir & 7;
            #pragma unroll
            for (int di = 0; di < 3; ++di) {
                int ii = ib + di - 1; ii = (ii < 0) ? ii + 10 : ((ii > 9) ? ii - 10 : ii);
                #pragma unroll
                for (int dj = 0; dj < 3; ++dj) {
                    int jj = jb + dj - 1; jj = (jj < 0) ? jj + 10 : ((jj > 9) ? jj - 10 : jj);
                    int rr = ii * 10 + jj;
                    float s = 0.f;
                    #pragma unroll
                    for (int t = 0; t < 8; ++t)
                        s += av[t] * f1sT[(CF + t) * F1STR + rr];
                    p[di * 3 + dj] = s;
                }
            }
            float mx = p[0];
            #pragma unroll
            for (int t = 1; t < 9; ++t) mx = fmaxf(mx, p[t]);
            float h[9], se = 0.f;
            #pragma unroll
            for (int t = 0; t < 9; ++t) { h[t] = __expf((p[t] - mx) * 0.1f); se += h[t]; }
            float inv = 1.f / se;
            float ex = 0.f, ey = 0.f;
            #pragma unroll
            for (int di = 0; di < 3; ++di)
                #pragma unroll
                for (int dj = 0; dj < 3; ++dj) {
                    ex += h[di * 3 + dj] * (float)(dj - 1);
                    ey += h[di * 3 + dj] * (float)(di - 1);
                }
            ex *= inv; ey *= inv;

            float mk0x = mk0[2 * m], mk0y = mk0[2 * m + 1];
            float mk1x = mk1[2 * m], mk1y = mk1[2 * m + 1];
            size_t base = (size_t)MTOT * 4096;
            out[base + 2 * m]     = mk0x + dlx * 2.f;
            out[base + 2 * m + 1] = mk0y + dly * 2.f;
            out[base + 2 * MTOT + 2 * m]     = mk1x + drx * 2.f + ex * 2.f;
            out[base + 2 * MTOT + 2 * m + 1] = mk1y + dry * 2.f + ey * 2.f;
        }
    }
}

extern "C" void kernel_launch(void* const* d_in, const int* in_sizes, int n_in,
                              void* d_out, int out_size)
{
    const float* feat0 = (const float*)d_in[0];
    const float* feat1 = (const float*)d_in[1];
    const float* mk0   = (const float*)d_in[2];
    const float* mk1   = (const float*)d_in[3];
    float* out = (float*)d_out;

    cudaFuncSetAttribute(fine_matching_kernel,
                         cudaFuncAttributeMaxDynamicSharedMemorySize, SMEM_BYTES);
    fine_matching_kernel<<<MTOT, 256, SMEM_BYTES>>>(feat0, feat1, mk0, mk1, out);
}

// round 7
// speedup vs baseline: 2.1778x; 1.2015x over previous
#include <cuda_runtime.h>
#include <cstdint>

#define MTOT 8192
#define LW   64      // ww
#define RW   100     // WP*WP
#define CD   128
#define CF   120     // C - SLICE
#define NPAD 104     // padded N (13 n-tiles of 8)
#define F1STR 132    // f1 smem row stride (floats): banks 4*gid+ctid distinct
#define CSTR  104    // conf row stride
#define ASTR  28     // f0 chunk row stride: banks -4*gid+ctid distinct
#define CHUNK_C 24   // channels per f0 chunk (3 k-tiles)
#define F0CSZ (64*ASTR)

typedef unsigned int u32;

__device__ __forceinline__ u32 tf32_hi(float x) {
    u32 r; asm("cvt.rna.tf32.f32 %0, %1;" : "=r"(r) : "f"(x)); return r;
}
__device__ __forceinline__ void split_tf32(float x, u32& hi, u32& lo) {
    hi = tf32_hi(x);
    lo = tf32_hi(x - __uint_as_float(hi));
}
__device__ __forceinline__ void mma_tf32(float c[4],
                                         u32 a0, u32 a1, u32 a2, u32 a3,
                                         u32 b0, u32 b1) {
    asm volatile(
        "mma.sync.aligned.m16n8k8.row.col.f32.tf32.tf32.f32 "
        "{%0,%1,%2,%3}, {%4,%5,%6,%7}, {%8,%9}, {%0,%1,%2,%3};"
        : "+f"(c[0]), "+f"(c[1]), "+f"(c[2]), "+f"(c[3])
        : "r"(a0), "r"(a1), "r"(a2), "r"(a3), "r"(b0), "r"(b1));
}
__device__ __forceinline__ void cp_async16(u32 smem_addr, const void* gptr) {
    asm volatile("cp.async.ca.shared.global [%0], [%1], 16;\n"
                 :: "r"(smem_addr), "l"(gptr) : "memory");
}
#define CP_COMMIT() asm volatile("cp.async.commit_group;\n" ::: "memory")
#define CP_WAIT(N)  asm volatile("cp.async.wait_group %0;\n" :: "n"(N) : "memory")

// ---- shared memory layout (floats) ----
// f1s  [0, 13728)       : 104 rows x 132 (feat1 rows, raw, row-major)
//                         conf (64 x 104 = 6656) aliases [0,6656) post-mainloop
// ff1  [13728, 14528)   : 100 x 8 raw ff channels (relocated pre-mainloop)
// misc [14528, 14896)
// f0c  [14896, 18480)   : 2 x (64 x 28) chunk double-buffer
#define OFF_F1   0
#define OFF_CONF 0
#define OFF_FF1  13728
#define OFF_RMAX 14528
#define OFF_RINV 14592
#define OFF_CMAX 14656
#define OFF_CINV 14760
#define OFF_REDV 14864
#define OFF_REDI 14880
#define OFF_F0C  14896
#define SMEM_FLOATS 18480
#define SMEM_BYTES (SMEM_FLOATS * 4)

__global__ void __launch_bounds__(256, 3)
fine_matching_kernel(const float* __restrict__ feat0,
                     const float* __restrict__ feat1,
                     const float* __restrict__ mk0,
                     const float* __restrict__ mk1,
                     float* __restrict__ out)
{
    extern __shared__ float smem[];
    float* f1s  = smem + OFF_F1;
    float* conf = smem + OFF_CONF;
    float* ff1  = smem + OFF_FF1;
    float* rmax = smem + OFF_RMAX;
    float* rinv = smem + OFF_RINV;
    float* cmax = smem + OFF_CMAX;
    float* cinv = smem + OFF_CINV;
    float* redv = smem + OFF_REDV;
    int*   redi = (int*)(smem + OFF_REDI);
    float* f0c  = smem + OFF_F0C;

    const int m    = blockIdx.x;
    const int tid  = threadIdx.x;
    const int warp = tid >> 5;
    const int lane = tid & 31;

    u32 smem_u32;
    { unsigned long long gp = __cvta_generic_to_shared(smem); smem_u32 = (u32)gp; }

    const float* f0base = feat0 + (size_t)m * (LW * CD);
    const float* f1base = feat1 + (size_t)m * (RW * CD);

    // ---- stage f0 chunk (ck) into buffer (buf): 64 l x 24 c, 16B cp.async ----
    #define STAGE_F0(buf, ck) do {                                             \
        for (int _j = tid; _j < 384; _j += 256) {                              \
            int _l = _j / 6, _cc = (_j % 6) * 4;                               \
            cp_async16(smem_u32 + (u32)(OFF_F0C + (buf)*F0CSZ + _l*ASTR + _cc)*4, \
                       f0base + _l * CD + (ck) * CHUNK_C + _cc);               \
        }                                                                      \
    } while (0)

    // ---- stage f1 rows raw (row-major, stride 132) + chunk0 : group A ----
    for (int i = tid; i < 3200; i += 256) {
        int r = i >> 5, q = (i & 31) * 4;
        cp_async16(smem_u32 + (u32)(OFF_F1 + r * F1STR + q) * 4,
                   f1base + r * CD + q);
    }
    STAGE_F0(0, 0);
    CP_COMMIT();            // group A: f1 + chunk0
    STAGE_F0(1, 1);
    CP_COMMIT();            // group B: chunk1
    CP_WAIT(1);             // group A resident
    __syncthreads();

    // relocate ff channels (c 120..127) so conf can alias f1s low rows later
    for (int i = tid; i < 800; i += 256) {
        int r = i >> 3, k = i & 7;
        ff1[i] = f1s[r * F1STR + 120 + k];
    }
    // no barrier needed: per-thread program order puts this before mainloop,
    // and conf stores happen only after the post-mainloop __syncthreads.

    // ---- tensor-core mainloop: 3xTF32 m16n8k8 ----
    const int gid  = lane >> 2;      // 0..7
    const int ctid = lane & 3;       // 0..3
    const int wm   = warp & 3;       // M-tile group: l0 = wm*16
    const int wn   = warp >> 2;      // N half
    const int l0   = wm * 16;
    const int nbase  = wn * 56;
    const int ntiles = wn ? 6 : 7;

    float c[7][4];
    #pragma unroll
    for (int j = 0; j < 7; ++j)
        { c[j][0] = 0.f; c[j][1] = 0.f; c[j][2] = 0.f; c[j][3] = 0.f; }

    const int aOff = (l0 + gid) * ASTR + ctid;
    const int bOff = (nbase + gid) * F1STR + ctid;

    #pragma unroll 1
    for (int ck = 0; ck < 5; ++ck) {
        const int buf = ck & 1;
        const float* ab = &f0c[buf * F0CSZ + aOff];
        #pragma unroll
        for (int kt = 0; kt < 3; ++kt) {
            const int c0k = ck * CHUNK_C + kt * 8;
            // A fragment (scaled by 1/128 exactly), split hi/lo
            const float* ap = ab + kt * 8;
            float af0 = ap[0]          * 0.0078125f;
            float af1 = ap[8 * ASTR]   * 0.0078125f;
            float af2 = ap[4]          * 0.0078125f;
            float af3 = ap[8 * ASTR + 4] * 0.0078125f;
            u32 ah0, al0, ah1, al1, ah2, al2, ah3, al3;
            split_tf32(af0, ah0, al0);
            split_tf32(af1, ah1, al1);
            split_tf32(af2, ah2, al2);
            split_tf32(af3, ah3, al3);
            #pragma unroll
            for (int j = 0; j < 7; ++j) {
                if (j < ntiles) {
                    const float* bp = &f1s[bOff + j * (8 * F1STR) + c0k];
                    float bf0 = bp[0];
                    float bf1 = bp[4];
                    u32 bh0, bl0, bh1, bl1;
                    split_tf32(bf0, bh0, bl0);
                    split_tf32(bf1, bh1, bl1);
                    mma_tf32(c[j], ah0, ah1, ah2, ah3, bh0, bh1);
                    mma_tf32(c[j], ah0, ah1, ah2, ah3, bl0, bl1);
                    mma_tf32(c[j], al0, al1, al2, al3, bh0, bh1);
                }
            }
        }
        __syncthreads();                     // buf fully consumed by all warps
        if (ck <= 2) {
            STAGE_F0(buf, ck + 2);           // refill freed buffer
            CP_COMMIT();
            CP_WAIT(1);                      // next chunk resident
            __syncthreads();
        } else if (ck == 3) {
            CP_WAIT(0);
            __syncthreads();
        }
    }
    // last loop iteration ended with __syncthreads(): all f1s reads complete,
    // conf may now alias the f1s low region.

    // ---- store conf from C fragments (cols 100..103 are garbage, never read) ----
    {
        const int rowa = (l0 + gid) * CSTR + 2 * ctid;
        #pragma unroll
        for (int j = 0; j < 7; ++j) {
            if (j < ntiles) {
                int o = rowa + nbase + 8 * j;
                *(float2*)&conf[o]            = make_float2(c[j][0], c[j][1]);
                *(float2*)&conf[o + 8 * CSTR] = make_float2(c[j][2], c[j][3]);
            }
        }
    }
    __syncthreads();

    // ---- softmax stats, split across warps ----
    if (warp < 4) {
        // row stats (axis=2 over 100 r): warps 0-3, 16 rows each
        #pragma unroll 4
        for (int q = 0; q < 16; ++q) {
            int l = warp * 16 + q;
            const float* row = &conf[l * CSTR];
            float v0 = row[lane], v1 = row[lane + 32], v2 = row[lane + 64];
            float v3 = (lane < 4) ? row[lane + 96] : -1e30f;
            float mx = fmaxf(fmaxf(v0, v1), fmaxf(v2, v3));
            #pragma unroll
            for (int o = 16; o; o >>= 1) mx = fmaxf(mx, __shfl_xor_sync(~0u, mx, o));
            float s = __expf(v0 - mx) + __expf(v1 - mx) + __expf(v2 - mx)
                    + __expf(v3 - mx);
            #pragma unroll
            for (int o = 16; o; o >>= 1) s += __shfl_xor_sync(~0u, s, o);
            if (lane == 0) { rmax[l] = mx; rinv[l] = 1.f / s; }
        }
    } else {
        // col stats (axis=1 over 64 l): warps 4-7, one column per thread
        int r = (warp - 4) * 32 + lane;
        if (r < RW) {
            float m0 = -1e30f, m1 = -1e30f, m2 = -1e30f, m3 = -1e30f;
            #pragma unroll
            for (int l = 0; l < LW; l += 4) {
                m0 = fmaxf(m0, conf[(l + 0) * CSTR + r]);
                m1 = fmaxf(m1, conf[(l + 1) * CSTR + r]);
                m2 = fmaxf(m2, conf[(l + 2) * CSTR + r]);
                m3 = fmaxf(m3, conf[(l + 3) * CSTR + r]);
            }
            float mx = fmaxf(fmaxf(m0, m1), fmaxf(m2, m3));
            float s0 = 0.f, s1 = 0.f, s2 = 0.f, s3 = 0.f;
            #pragma unroll
            for (int l = 0; l < LW; l += 4) {
                s0 += __expf(conf[(l + 0) * CSTR + r] - mx);
                s1 += __expf(conf[(l + 1) * CSTR + r] - mx);
                s2 += __expf(conf[(l + 2) * CSTR + r] - mx);
                s3 += __expf(conf[(l + 3) * CSTR + r] - mx);
            }
            cmax[r] = mx; cinv[r] = 1.f / ((s0 + s1) + (s2 + s3));
        }
    }
    __syncthreads();

    // ---- cropped sm write + argmax (first-occurrence tie-break) ----
    const int rc = tid & 63;
    const int r  = (rc >> 3) * 10 + (rc & 7) + 11;
    const float cm = cmax[r], ci = cinv[r];
    const int lb = tid >> 6;
    float bv = -1e30f; int bi = 0;
    float* outm = out + (size_t)m * 4096;
    #pragma unroll
    for (int e8 = 0; e8 < 16; ++e8) {
        int l = e8 * 4 + lb;
        float v = conf[l * CSTR + r];
        float s = __expf(2.f * v - rmax[l] - cm) * rinv[l] * ci;
        int flat = l * 64 + rc;
        outm[flat] = s;
        if (s > bv) { bv = s; bi = flat; }
    }
    #pragma unroll
    for (int o = 16; o; o >>= 1) {
        float v2 = __shfl_xor_sync(~0u, bv, o);
        int   i2 = __shfl_xor_sync(~0u, bi, o);
        if (v2 > bv || (v2 == bv && i2 < bi)) { bv = v2; bi = i2; }
    }
    if (lane == 0) { redv[warp] = bv; redi[warp] = bi; }
    __syncthreads();

    // ---- warp 0: final reduce + epilogue ----
    if (warp == 0) {
        float v = (lane < 8) ? redv[lane] : -1e30f;
        int   i = (lane < 8) ? redi[lane] : 0x7fffffff;
        #pragma unroll
        for (int o = 4; o; o >>= 1) {
            float v2 = __shfl_xor_sync(~0u, v, o);
            int   i2 = __shfl_xor_sync(~0u, i, o);
            if (v2 > v || (v2 == v && i2 < i)) { v = v2; i = i2; }
        }
        if (lane == 0) {
            int idx = i;
            int il = idx >> 6, ir = idx & 63;
            float dlx = (float)(il & 7) - 3.5f, dly = (float)(il >> 3) - 3.5f;
            float drx = (float)(ir & 7) - 3.5f, dry = (float)(ir >> 3) - 3.5f;

            // last 8 channels of f0 row il, from global (L2-hot)
            float4 av0 = __ldg((const float4*)(f0base + il * CD + CF));
            float4 av1 = __ldg((const float4*)(f0base + il * CD + CF + 4));
            float av[8] = {av0.x, av0.y, av0.z, av0.w, av1.x, av1.y, av1.z, av1.w};

            // 3x3 conf_ff patch from raw ff1; scales folded into the exponent:
            // heat exponent = (p_raw - max_raw) * (1/sqrt(8)) / TEMP
            float p[9];
            int ib = ir >> 3, jb = ir & 7;
            #pragma unroll
            for (int di = 0; di < 3; ++di) {
                int ii = ib + di - 1; ii = (ii < 0) ? ii + 10 : ((ii > 9) ? ii - 10 : ii);
                #pragma unroll
                for (int dj = 0; dj < 3; ++dj) {
                    int jj = jb + dj - 1; jj = (jj < 0) ? jj + 10 : ((jj > 9) ? jj - 10 : jj);
                    int rr = ii * 10 + jj;
                    float s = 0.f;
                    #pragma unroll
                    for (int t = 0; t < 8; ++t)
                        s += av[t] * ff1[rr * 8 + t];
                    p[di * 3 + dj] = s;
                }
            }
            float mx = p[0];
            #pragma unroll
            for (int t = 1; t < 9; ++t) mx = fmaxf(mx, p[t]);
            const float escale = 0.35355339059327373f * 0.1f;
            float h[9], se = 0.f;
            #pragma unroll
            for (int t = 0; t < 9; ++t) { h[t] = __expf((p[t] - mx) * escale); se += h[t]; }
            float inv = 1.f / se;
            float ex = 0.f, ey = 0.f;
            #pragma unroll
            for (int di = 0; di < 3; ++di)
                #pragma unroll
                for (int dj = 0; dj < 3; ++dj) {
                    ex += h[di * 3 + dj] * (float)(dj - 1);
                    ey += h[di * 3 + dj] * (float)(di - 1);
                }
            ex *= inv; ey *= inv;

            float mk0x = mk0[2 * m], mk0y = mk0[2 * m + 1];
            float mk1x = mk1[2 * m], mk1y = mk1[2 * m + 1];
            size_t base = (size_t)MTOT * 4096;
            out[base + 2 * m]     = mk0x + dlx * 2.f;
            out[base + 2 * m + 1] = mk0y + dly * 2.f;
            out[base + 2 * MTOT + 2 * m]     = mk1x + drx * 2.f + ex * 2.f;
            out[base + 2 * MTOT + 2 * m + 1] = mk1y + dry * 2.f + ey * 2.f;
        }
    }
}

extern "C" void kernel_launch(void* const* d_in, const int* in_sizes, int n_in,
                              void* d_out, int out_size)
{
    const float* feat0 = (const float*)d_in[0];
    const float* feat1 = (const float*)d_in[1];
    const float* mk0   = (const float*)d_in[2];
    const float* mk1   = (const float*)d_in[3];
    float* out = (float*)d_out;

    cudaFuncSetAttribute(fine_matching_kernel,
                         cudaFuncAttributeMaxDynamicSharedMemorySize, SMEM_BYTES);
    fine_matching_kernel<<<MTOT, 256, SMEM_BYTES>>>(feat0, feat1, mk0, mk1, out);
}

// round 8
// speedup vs baseline: 2.5113x; 1.1531x over previous
#include <cuda_runtime.h>
#include <cstdint>

#define MTOT 8192
#define LW   64      // ww
#define RW   100     // WP*WP
#define CD   128
#define CF   120     // C - SLICE
#define NPAD 104     // padded N (13 n-tiles of 8)
#define F1STR 132    // f1 smem row stride (floats): banks 4*gid+ctid distinct
#define CSTR  104    // conf row stride
#define ASTR  28     // f0 chunk row stride: banks -4*gid+ctid distinct
#define CHUNK_C 24   // channels per f0 chunk (3 k-tiles)
#define F0CSZ (64*ASTR)

typedef unsigned int u32;

// Truncation split: hi = top-19-bit truncation (valid tf32 operand),
// lo = exact remainder (FSUB). No CVT instructions needed: the tensor core
// reads only the top 19 bits of each 32-bit tf32 operand, and lo's own
// truncation error is 2^-22-level (same order as the dropped lo*lo term).
__device__ __forceinline__ void splitm(float x, u32& hi, u32& lo) {
    u32 h = __float_as_uint(x) & 0xFFFFE000u;
    hi = h;
    lo = __float_as_uint(x - __uint_as_float(h));
}
__device__ __forceinline__ void mma_tf32(float c[4],
                                         u32 a0, u32 a1, u32 a2, u32 a3,
                                         u32 b0, u32 b1) {
    asm volatile(
        "mma.sync.aligned.m16n8k8.row.col.f32.tf32.tf32.f32 "
        "{%0,%1,%2,%3}, {%4,%5,%6,%7}, {%8,%9}, {%0,%1,%2,%3};"
        : "+f"(c[0]), "+f"(c[1]), "+f"(c[2]), "+f"(c[3])
        : "r"(a0), "r"(a1), "r"(a2), "r"(a3), "r"(b0), "r"(b1));
}
__device__ __forceinline__ void cp_async16(u32 smem_addr, const void* gptr) {
    asm volatile("cp.async.ca.shared.global [%0], [%1], 16;\n"
                 :: "r"(smem_addr), "l"(gptr) : "memory");
}
#define CP_COMMIT() asm volatile("cp.async.commit_group;\n" ::: "memory")
#define CP_WAIT(N)  asm volatile("cp.async.wait_group %0;\n" :: "n"(N) : "memory")

// ---- shared memory layout (floats) ----
// f1s  [0, 13728)       : 104 rows x 132 (feat1 rows, raw, row-major)
//                         conf (64 x 104 = 6656) aliases [0,6656) post-mainloop
// ff1  [13728, 14528)   : 100 x 8 raw ff channels (relocated pre-mainloop)
// misc [14528, 14896)
// f0c  [14896, 18480)   : 2 x (64 x 28) chunk double-buffer
#define OFF_F1   0
#define OFF_CONF 0
#define OFF_FF1  13728
#define OFF_RMAX 14528
#define OFF_RINV 14592
#define OFF_CMAX 14656
#define OFF_CINV 14760
#define OFF_REDV 14864
#define OFF_REDI 14880
#define OFF_F0C  14896
#define SMEM_FLOATS 18480
#define SMEM_BYTES (SMEM_FLOATS * 4)

__global__ void __launch_bounds__(256, 3)
fine_matching_kernel(const float* __restrict__ feat0,
                     const float* __restrict__ feat1,
                     const float* __restrict__ mk0,
                     const float* __restrict__ mk1,
                     float* __restrict__ out)
{
    extern __shared__ float smem[];
    float* f1s  = smem + OFF_F1;
    float* conf = smem + OFF_CONF;
    float* ff1  = smem + OFF_FF1;
    float* rmax = smem + OFF_RMAX;
    float* rinv = smem + OFF_RINV;
    float* cmax = smem + OFF_CMAX;
    float* cinv = smem + OFF_CINV;
    float* redv = smem + OFF_REDV;
    int*   redi = (int*)(smem + OFF_REDI);
    float* f0c  = smem + OFF_F0C;

    const int m    = blockIdx.x;
    const int tid  = threadIdx.x;
    const int warp = tid >> 5;
    const int lane = tid & 31;

    u32 smem_u32;
    { unsigned long long gp = __cvta_generic_to_shared(smem); smem_u32 = (u32)gp; }

    const float* f0base = feat0 + (size_t)m * (LW * CD);
    const float* f1base = feat1 + (size_t)m * (RW * CD);

    // ---- stage f0 chunk (ck) into buffer (buf): 64 l x 24 c, 16B cp.async ----
    #define STAGE_F0(buf, ck) do {                                             \
        for (int _j = tid; _j < 384; _j += 256) {                              \
            int _l = _j / 6, _cc = (_j % 6) * 4;                               \
            cp_async16(smem_u32 + (u32)(OFF_F0C + (buf)*F0CSZ + _l*ASTR + _cc)*4, \
                       f0base + _l * CD + (ck) * CHUNK_C + _cc);               \
        }                                                                      \
    } while (0)

    // ---- stage f1 rows raw (row-major, stride 132) + chunk0 : group A ----
    for (int i = tid; i < 3200; i += 256) {
        int r = i >> 5, q = (i & 31) * 4;
        cp_async16(smem_u32 + (u32)(OFF_F1 + r * F1STR + q) * 4,
                   f1base + r * CD + q);
    }
    STAGE_F0(0, 0);
    CP_COMMIT();            // group A: f1 + chunk0
    STAGE_F0(1, 1);
    CP_COMMIT();            // group B: chunk1
    CP_WAIT(1);             // group A resident
    __syncthreads();

    // relocate ff channels (c 120..127) so conf can alias f1s low rows later
    for (int i = tid; i < 800; i += 256) {
        int r = i >> 3, k = i & 7;
        ff1[i] = f1s[r * F1STR + 120 + k];
    }
    // no barrier needed: per-thread program order puts this before mainloop,
    // and conf stores happen only after the post-mainloop __syncthreads.

    // ---- tensor-core mainloop: 3xTF32 m16n8k8, CVT-free truncation splits ----
    const int gid  = lane >> 2;      // 0..7
    const int ctid = lane & 3;       // 0..3
    const int wm   = warp & 3;       // M-tile group: l0 = wm*16
    const int wn   = warp >> 2;      // N half
    const int l0   = wm * 16;
    const int nbase = wn * 56;       // wn0: tiles 0..6 (n 0..55), wn1: 6 tiles (n 56..103)

    float c[7][4];
    #pragma unroll
    for (int j = 0; j < 7; ++j)
        { c[j][0] = 0.f; c[j][1] = 0.f; c[j][2] = 0.f; c[j][3] = 0.f; }

    const int aOff = (l0 + gid) * ASTR + ctid;
    const int bOff = (nbase + gid) * F1STR + ctid;

    // one B-tile worth of loads + splits + 3 MMAs
    #define BMMA(cj, bp) do {                                                  \
        float _bf0 = (bp)[0];                                                  \
        float _bf1 = (bp)[4];                                                  \
        u32 _bh0, _bl0, _bh1, _bl1;                                            \
        splitm(_bf0, _bh0, _bl0);                                              \
        splitm(_bf1, _bh1, _bl1);                                              \
        mma_tf32(cj, ah0, ah1, ah2, ah3, _bh0, _bh1);                          \
        mma_tf32(cj, ah0, ah1, ah2, ah3, _bl0, _bl1);                          \
        mma_tf32(cj, al0, al1, al2, al3, _bh0, _bh1);                          \
    } while (0)

    #pragma unroll 1
    for (int ck = 0; ck < 5; ++ck) {
        const int buf = ck & 1;
        const float* ab = &f0c[buf * F0CSZ + aOff];
        #pragma unroll
        for (int kt = 0; kt < 3; ++kt) {
            const int c0k = ck * CHUNK_C + kt * 8;
            // A fragment (scaled by 1/128 exactly; scale commutes with trunc)
            const float* ap = ab + kt * 8;
            float af0 = ap[0]            * 0.0078125f;
            float af1 = ap[8 * ASTR]     * 0.0078125f;
            float af2 = ap[4]            * 0.0078125f;
            float af3 = ap[8 * ASTR + 4] * 0.0078125f;
            u32 ah0, al0, ah1, al1, ah2, al2, ah3, al3;
            splitm(af0, ah0, al0);
            splitm(af1, ah1, al1);
            splitm(af2, ah2, al2);
            splitm(af3, ah3, al3);
            const float* bbase = &f1s[bOff + c0k];
            #pragma unroll
            for (int j = 0; j < 6; ++j)
                BMMA(c[j], bbase + j * (8 * F1STR));
            if (wn == 0)                      // uniform branch per warp
                BMMA(c[6], bbase + 6 * (8 * F1STR));
        }
        __syncthreads();                     // buf fully consumed by all warps
        if (ck <= 2) {
            STAGE_F0(buf, ck + 2);           // refill freed buffer
            CP_COMMIT();
            CP_WAIT(1);                      // next chunk resident
            __syncthreads();
        } else if (ck == 3) {
            CP_WAIT(0);
            __syncthreads();
        }
    }
    // last loop iteration ended with __syncthreads(): all f1s reads complete,
    // conf may now alias the f1s low region.

    // ---- store conf from C fragments (cols 100..103 are garbage, never read) ----
    {
        const int rowa = (l0 + gid) * CSTR + 2 * ctid;
        const int ntiles = wn ? 6 : 7;
        #pragma unroll
        for (int j = 0; j < 7; ++j) {
            if (j < ntiles) {
                int o = rowa + nbase + 8 * j;
                *(float2*)&conf[o]            = make_float2(c[j][0], c[j][1]);
                *(float2*)&conf[o + 8 * CSTR] = make_float2(c[j][2], c[j][3]);
            }
        }
    }
    __syncthreads();

    // ---- softmax stats, split across warps ----
    if (warp < 4) {
        // row stats (axis=2 over 100 r): warps 0-3, 16 rows each
        #pragma unroll 4
        for (int q = 0; q < 16; ++q) {
            int l = warp * 16 + q;
            const float* row = &conf[l * CSTR];
            float v0 = row[lane], v1 = row[lane + 32], v2 = row[lane + 64];
            float v3 = (lane < 4) ? row[lane + 96] : -1e30f;
            float mx = fmaxf(fmaxf(v0, v1), fmaxf(v2, v3));
            #pragma unroll
            for (int o = 16; o; o >>= 1) mx = fmaxf(mx, __shfl_xor_sync(~0u, mx, o));
            float s = __expf(v0 - mx) + __expf(v1 - mx) + __expf(v2 - mx)
                    + __expf(v3 - mx);
            #pragma unroll
            for (int o = 16; o; o >>= 1) s += __shfl_xor_sync(~0u, s, o);
            if (lane == 0) { rmax[l] = mx; rinv[l] = 1.f / s; }
        }
    } else {
        // col stats (axis=1 over 64 l): warps 4-7, one column per thread
        int r = (warp - 4) * 32 + lane;
        if (r < RW) {
            float m0 = -1e30f, m1 = -1e30f, m2 = -1e30f, m3 = -1e30f;
            #pragma unroll
            for (int l = 0; l < LW; l += 4) {
                m0 = fmaxf(m0, conf[(l + 0) * CSTR + r]);
                m1 = fmaxf(m1, conf[(l + 1) * CSTR + r]);
                m2 = fmaxf(m2, conf[(l + 2) * CSTR + r]);
                m3 = fmaxf(m3, conf[(l + 3) * CSTR + r]);
            }
            float mx = fmaxf(fmaxf(m0, m1), fmaxf(m2, m3));
            float s0 = 0.f, s1 = 0.f, s2 = 0.f, s3 = 0.f;
            #pragma unroll
            for (int l = 0; l < LW; l += 4) {
                s0 += __expf(conf[(l + 0) * CSTR + r] - mx);
                s1 += __expf(conf[(l + 1) * CSTR + r] - mx);
                s2 += __expf(conf[(l + 2) * CSTR + r] - mx);
                s3 += __expf(conf[(l + 3) * CSTR + r] - mx);
            }
            cmax[r] = mx; cinv[r] = 1.f / ((s0 + s1) + (s2 + s3));
        }
    }
    __syncthreads();

    // ---- cropped sm write + argmax (first-occurrence tie-break) ----
    const int rc = tid & 63;
    const int r  = (rc >> 3) * 10 + (rc & 7) + 11;
    const float cm = cmax[r], ci = cinv[r];
    const int lb = tid >> 6;
    float bv = -1e30f; int bi = 0;
    float* outm = out + (size_t)m * 4096;
    #pragma unroll
    for (int e8 = 0; e8 < 16; ++e8) {
        int l = e8 * 4 + lb;
        float v = conf[l * CSTR + r];
        float s = __expf(2.f * v - rmax[l] - cm) * rinv[l] * ci;
        int flat = l * 64 + rc;
        outm[flat] = s;
        if (s > bv) { bv = s; bi = flat; }
    }
    #pragma unroll
    for (int o = 16; o; o >>= 1) {
        float v2 = __shfl_xor_sync(~0u, bv, o);
        int   i2 = __shfl_xor_sync(~0u, bi, o);
        if (v2 > bv || (v2 == bv && i2 < bi)) { bv = v2; bi = i2; }
    }
    if (lane == 0) { redv[warp] = bv; redi[warp] = bi; }
    __syncthreads();

    // ---- warp 0: final reduce + epilogue ----
    if (warp == 0) {
        float v = (lane < 8) ? redv[lane] : -1e30f;
        int   i = (lane < 8) ? redi[lane] : 0x7fffffff;
        #pragma unroll
        for (int o = 4; o; o >>= 1) {
            float v2 = __shfl_xor_sync(~0u, v, o);
            int   i2 = __shfl_xor_sync(~0u, i, o);
            if (v2 > v || (v2 == v && i2 < i)) { v = v2; i = i2; }
        }
        if (lane == 0) {
            int idx = i;
            int il = idx >> 6, ir = idx & 63;
            float dlx = (float)(il & 7) - 3.5f, dly = (float)(il >> 3) - 3.5f;
            float drx = (float)(ir & 7) - 3.5f, dry = (float)(ir >> 3) - 3.5f;

            // last 8 channels of f0 row il, from global (L2-hot)
            float4 av0 = __ldg((const float4*)(f0base + il * CD + CF));
            float4 av1 = __ldg((const float4*)(f0base + il * CD + CF + 4));
            float av[8] = {av0.x, av0.y, av0.z, av0.w, av1.x, av1.y, av1.z, av1.w};

            // 3x3 conf_ff patch from raw ff1; scales folded into the exponent
            float p[9];
            int ib = ir >> 3, jb = ir & 7;
            #pragma unroll
            for (int di = 0; di < 3; ++di) {
                int ii = ib + di - 1; ii = (ii < 0) ? ii + 10 : ((ii > 9) ? ii - 10 : ii);
                #pragma unroll
                for (int dj = 0; dj < 3; ++dj) {
                    int jj = jb + dj - 1; jj = (jj < 0) ? jj + 10 : ((jj > 9) ? jj - 10 : jj);
                    int rr = ii * 10 + jj;
                    float s = 0.f;
                    #pragma unroll
                    for (int t = 0; t < 8; ++t)
                        s += av[t] * ff1[rr * 8 + t];
                    p[di * 3 + dj] = s;
                }
            }
            float mx = p[0];
            #pragma unroll
            for (int t = 1; t < 9; ++t) mx = fmaxf(mx, p[t]);
            const float escale = 0.35355339059327373f * 0.1f;
            float h[9], se = 0.f;
            #pragma unroll
            for (int t = 0; t < 9; ++t) { h[t] = __expf((p[t] - mx) * escale); se += h[t]; }
            float inv = 1.f / se;
            float ex = 0.f, ey = 0.f;
            #pragma unroll
            for (int di = 0; di < 3; ++di)
                #pragma unroll
                for (int dj = 0; dj < 3; ++dj) {
                    ex += h[di * 3 + dj] * (float)(dj - 1);
                    ey += h[di * 3 + dj] * (float)(di - 1);
                }
            ex *= inv; ey *= inv;

            float mk0x = mk0[2 * m], mk0y = mk0[2 * m + 1];
            float mk1x = mk1[2 * m], mk1y = mk1[2 * m + 1];
            size_t base = (size_t)MTOT * 4096;
            out[base + 2 * m]     = mk0x + dlx * 2.f;
            out[base + 2 * m + 1] = mk0y + dly * 2.f;
            out[base + 2 * MTOT + 2 * m]     = mk1x + drx * 2.f + ex * 2.f;
            out[base + 2 * MTOT + 2 * m + 1] = mk1y + dry * 2.f + ey * 2.f;
        }
    }
}

extern "C" void kernel_launch(void* const* d_in, const int* in_sizes, int n_in,
                              void* d_out, int out_size)
{
    const float* feat0 = (const float*)d_in[0];
    const float* feat1 = (const float*)d_in[1];
    const float* mk0   = (const float*)d_in[2];
    const float* mk1   = (const float*)d_in[3];
    float* out = (float*)d_out;

    cudaFuncSetAttribute(fine_matching_kernel,
                         cudaFuncAttributeMaxDynamicSharedMemorySize, SMEM_BYTES);
    fine_matching_kernel<<<MTOT, 256, SMEM_BYTES>>>(feat0, feat1, mk0, mk1, out);
}

// round 9
// speedup vs baseline: 2.8098x; 1.1189x over previous
#include <cuda_runtime.h>
#include <cstdint>

#define MTOT 8192
#define LW   64      // ww
#define RW   100     // WP*WP
#define CD   128
#define CF   120     // C - SLICE
#define CSTR  104    // conf row stride (mod 32 = 8: conflict-free both passes)
#define ASTR  28     // A chunk row stride: banks -4*gid+ctid distinct
#define BSTR  28     // B chunk row stride: same pattern
#define CHUNK_C 24   // channels per chunk (3 k-tiles)

typedef unsigned int u32;

// Truncation split: hi = top-19-bit truncation (valid tf32 operand),
// lo = exact remainder (FSUB). CVT-free; error ~2^-22 (lo's own truncation).
__device__ __forceinline__ void splitm(float x, u32& hi, u32& lo) {
    u32 h = __float_as_uint(x) & 0xFFFFE000u;
    hi = h;
    lo = __float_as_uint(x - __uint_as_float(h));
}
__device__ __forceinline__ void mma_tf32(float c[4],
                                         u32 a0, u32 a1, u32 a2, u32 a3,
                                         u32 b0, u32 b1) {
    asm volatile(
        "mma.sync.aligned.m16n8k8.row.col.f32.tf32.tf32.f32 "
        "{%0,%1,%2,%3}, {%4,%5,%6,%7}, {%8,%9}, {%0,%1,%2,%3};"
        : "+f"(c[0]), "+f"(c[1]), "+f"(c[2]), "+f"(c[3])
        : "r"(a0), "r"(a1), "r"(a2), "r"(a3), "r"(b0), "r"(b1));
}
__device__ __forceinline__ void cp_async16(u32 smem_addr, const void* gptr) {
    asm volatile("cp.async.ca.shared.global [%0], [%1], 16;\n"
                 :: "r"(smem_addr), "l"(gptr) : "memory");
}
#define CP_COMMIT() asm volatile("cp.async.commit_group;\n" ::: "memory")
#define CP_WAIT(N)  asm volatile("cp.async.wait_group %0;\n" :: "n"(N) : "memory")

// ---- shared memory layout (floats) — fully streaming, 42.3 KB/CTA ----
// A bufs: 2 x (64 x 28)   [0, 3584)
// B bufs: 2 x (104 x 28)  [3584, 9408)
// conf (64 x 104 = 6656) aliases [0, 6656) after the mainloop
// ff1  : 100 x 8          [9408, 10208)
// misc : [10208, 10576)
#define OFF_A0   0
#define OFF_B0   3584
#define ABUFSZ   1792
#define BBUFSZ   2912
#define OFF_CONF 0
#define OFF_FF1  9408
#define OFF_RMAX 10208
#define OFF_RINV 10272
#define OFF_CMAX 10336
#define OFF_CINV 10440
#define OFF_REDV 10544
#define OFF_REDI 10560
#define SMEM_FLOATS 10576
#define SMEM_BYTES (SMEM_FLOATS * 4)

__global__ void __launch_bounds__(256, 4)
fine_matching_kernel(const float* __restrict__ feat0,
                     const float* __restrict__ feat1,
                     const float* __restrict__ mk0,
                     const float* __restrict__ mk1,
                     float* __restrict__ out)
{
    extern __shared__ float smem[];
    float* conf = smem + OFF_CONF;
    float* ff1  = smem + OFF_FF1;
    float* rmax = smem + OFF_RMAX;
    float* rinv = smem + OFF_RINV;
    float* cmax = smem + OFF_CMAX;
    float* cinv = smem + OFF_CINV;
    float* redv = smem + OFF_REDV;
    int*   redi = (int*)(smem + OFF_REDI);

    const int m    = blockIdx.x;
    const int tid  = threadIdx.x;
    const int warp = tid >> 5;
    const int lane = tid & 31;

    u32 smem_u32;
    { unsigned long long gp = __cvta_generic_to_shared(smem); smem_u32 = (u32)gp; }

    const float* f0base = feat0 + (size_t)m * (LW * CD);
    const float* f1base = feat1 + (size_t)m * (RW * CD);

    // ---- stage A+B chunk (ck) into buffer (buf) ----
    #define STAGE_AB(buf, ck) do {                                              \
        for (int _j = tid; _j < 384; _j += 256) {                               \
            int _l = _j / 6, _cc = (_j % 6) * 4;                                \
            cp_async16(smem_u32 + (u32)(OFF_A0 + (buf)*ABUFSZ + _l*ASTR + _cc)*4, \
                       f0base + _l * CD + (ck) * CHUNK_C + _cc);                \
        }                                                                       \
        for (int _j = tid; _j < 600; _j += 256) {                               \
            int _r = _j / 6, _cc = (_j % 6) * 4;                                \
            cp_async16(smem_u32 + (u32)(OFF_B0 + (buf)*BBUFSZ + _r*BSTR + _cc)*4, \
                       f1base + _r * CD + (ck) * CHUNK_C + _cc);                \
        }                                                                       \
    } while (0)

    // prologue: chunk0 + ff channels (group A), chunk1 (group B)
    STAGE_AB(0, 0);
    for (int j = tid; j < 200; j += 256) {
        int r = j >> 1, q = (j & 1) * 4;
        cp_async16(smem_u32 + (u32)(OFF_FF1 + r * 8 + q) * 4,
                   f1base + r * CD + 120 + q);
    }
    CP_COMMIT();
    STAGE_AB(1, 1);
    CP_COMMIT();
    CP_WAIT(1);             // group A resident
    __syncthreads();

    // ---- tensor-core mainloop: 3xTF32 m16n8k8, fully streamed ----
    const int gid  = lane >> 2;      // 0..7
    const int ctid = lane & 3;       // 0..3
    const int wm   = warp & 3;       // M-tile group: l0 = wm*16
    const int wn   = warp >> 2;      // N half
    const int l0   = wm * 16;
    const int nbase = wn * 56;       // wn0: 7 tiles (n 0..55), wn1: 6 tiles (56..103)

    float c[7][4];
    #pragma unroll
    for (int j = 0; j < 7; ++j)
        { c[j][0] = 0.f; c[j][1] = 0.f; c[j][2] = 0.f; c[j][3] = 0.f; }

    const int aOff = (l0 + gid) * ASTR + ctid;
    const int bOff = (nbase + gid) * BSTR + ctid;

    #define BMMA(cj, bp) do {                                                  \
        float _bf0 = (bp)[0];                                                  \
        float _bf1 = (bp)[4];                                                  \
        u32 _bh0, _bl0, _bh1, _bl1;                                            \
        splitm(_bf0, _bh0, _bl0);                                              \
        splitm(_bf1, _bh1, _bl1);                                              \
        mma_tf32(cj, ah0, ah1, ah2, ah3, _bh0, _bh1);                          \
        mma_tf32(cj, ah0, ah1, ah2, ah3, _bl0, _bl1);                          \
        mma_tf32(cj, al0, al1, al2, al3, _bh0, _bh1);                          \
    } while (0)

    #pragma unroll 1
    for (int ck = 0; ck < 5; ++ck) {
        const int buf = ck & 1;
        const float* ab = smem + OFF_A0 + buf * ABUFSZ + aOff;
        const float* bb = smem + OFF_B0 + buf * BBUFSZ + bOff;
        #pragma unroll
        for (int kt = 0; kt < 3; ++kt) {
            const float* ap = ab + kt * 8;
            float af0 = ap[0]            * 0.0078125f;
            float af1 = ap[8 * ASTR]     * 0.0078125f;
            float af2 = ap[4]            * 0.0078125f;
            float af3 = ap[8 * ASTR + 4] * 0.0078125f;
            u32 ah0, al0, ah1, al1, ah2, al2, ah3, al3;
            splitm(af0, ah0, al0);
            splitm(af1, ah1, al1);
            splitm(af2, ah2, al2);
            splitm(af3, ah3, al3);
            const float* bbase = bb + kt * 8;
            #pragma unroll
            for (int j = 0; j < 6; ++j)
                BMMA(c[j], bbase + j * (8 * BSTR));
            if (wn == 0)                      // uniform branch per warp
                BMMA(c[6], bbase + 6 * (8 * BSTR));
        }
        __syncthreads();                     // buf fully consumed by all warps
        if (ck <= 2) {
            STAGE_AB(buf, ck + 2);           // refill freed buffer
            CP_COMMIT();
            CP_WAIT(1);                      // next chunk resident
            __syncthreads();
        } else if (ck == 3) {
            CP_WAIT(0);
            __syncthreads();
        }
    }
    // final __syncthreads issued inside loop: all buffer reads complete,
    // conf may now alias the A/B buffer region.

    // ---- store conf from C fragments (cols 100..103 garbage, never read) ----
    {
        const int rowa = (l0 + gid) * CSTR + 2 * ctid;
        const int ntiles = wn ? 6 : 7;
        #pragma unroll
        for (int j = 0; j < 7; ++j) {
            if (j < ntiles) {
                int o = rowa + nbase + 8 * j;
                *(float2*)&conf[o]            = make_float2(c[j][0], c[j][1]);
                *(float2*)&conf[o + 8 * CSTR] = make_float2(c[j][2], c[j][3]);
            }
        }
    }
    __syncthreads();

    // ---- softmax stats, split across warps ----
    if (warp < 4) {
        // row stats (axis=2 over 100 r): warps 0-3, 16 rows each
        #pragma unroll 4
        for (int q = 0; q < 16; ++q) {
            int l = warp * 16 + q;
            const float* row = &conf[l * CSTR];
            float v0 = row[lane], v1 = row[lane + 32], v2 = row[lane + 64];
            float v3 = (lane < 4) ? row[lane + 96] : -1e30f;
            float mx = fmaxf(fmaxf(v0, v1), fmaxf(v2, v3));
            #pragma unroll
            for (int o = 16; o; o >>= 1) mx = fmaxf(mx, __shfl_xor_sync(~0u, mx, o));
            float s = __expf(v0 - mx) + __expf(v1 - mx) + __expf(v2 - mx)
                    + __expf(v3 - mx);
            #pragma unroll
            for (int o = 16; o; o >>= 1) s += __shfl_xor_sync(~0u, s, o);
            if (lane == 0) { rmax[l] = mx; rinv[l] = 1.f / s; }
        }
    } else {
        // col stats (axis=1 over 64 l): warps 4-7, one column per thread
        int r = (warp - 4) * 32 + lane;
        if (r < RW) {
            float m0 = -1e30f, m1 = -1e30f, m2 = -1e30f, m3 = -1e30f;
            #pragma unroll
            for (int l = 0; l < LW; l += 4) {
                m0 = fmaxf(m0, conf[(l + 0) * CSTR + r]);
                m1 = fmaxf(m1, conf[(l + 1) * CSTR + r]);
                m2 = fmaxf(m2, conf[(l + 2) * CSTR + r]);
                m3 = fmaxf(m3, conf[(l + 3) * CSTR + r]);
            }
            float mx = fmaxf(fmaxf(m0, m1), fmaxf(m2, m3));
            float s0 = 0.f, s1 = 0.f, s2 = 0.f, s3 = 0.f;
            #pragma unroll
            for (int l = 0; l < LW; l += 4) {
                s0 += __expf(conf[(l + 0) * CSTR + r] - mx);
                s1 += __expf(conf[(l + 1) * CSTR + r] - mx);
                s2 += __expf(conf[(l + 2) * CSTR + r] - mx);
                s3 += __expf(conf[(l + 3) * CSTR + r] - mx);
            }
            cmax[r] = mx; cinv[r] = 1.f / ((s0 + s1) + (s2 + s3));
        }
    }
    __syncthreads();

    // ---- cropped sm write + argmax (first-occurrence tie-break) ----
    const int rc = tid & 63;
    const int r  = (rc >> 3) * 10 + (rc & 7) + 11;
    const float cm = cmax[r], ci = cinv[r];
    const int lb = tid >> 6;
    float bv = -1e30f; int bi = 0;
    float* outm = out + (size_t)m * 4096;
    #pragma unroll
    for (int e8 = 0; e8 < 16; ++e8) {
        int l = e8 * 4 + lb;
        float v = conf[l * CSTR + r];
        float s = __expf(2.f * v - rmax[l] - cm) * rinv[l] * ci;
        int flat = l * 64 + rc;
        outm[flat] = s;
        if (s > bv) { bv = s; bi = flat; }
    }
    #pragma unroll
    for (int o = 16; o; o >>= 1) {
        float v2 = __shfl_xor_sync(~0u, bv, o);
        int   i2 = __shfl_xor_sync(~0u, bi, o);
        if (v2 > bv || (v2 == bv && i2 < bi)) { bv = v2; bi = i2; }
    }
    if (lane == 0) { redv[warp] = bv; redi[warp] = bi; }
    __syncthreads();

    // ---- warp 0: final reduce + epilogue ----
    if (warp == 0) {
        float v = (lane < 8) ? redv[lane] : -1e30f;
        int   i = (lane < 8) ? redi[lane] : 0x7fffffff;
        #pragma unroll
        for (int o = 4; o; o >>= 1) {
            float v2 = __shfl_xor_sync(~0u, v, o);
            int   i2 = __shfl_xor_sync(~0u, i, o);
            if (v2 > v || (v2 == v && i2 < i)) { v = v2; i = i2; }
        }
        if (lane == 0) {
            int idx = i;
            int il = idx >> 6, ir = idx & 63;
            float dlx = (float)(il & 7) - 3.5f, dly = (float)(il >> 3) - 3.5f;
            float drx = (float)(ir & 7) - 3.5f, dry = (float)(ir >> 3) - 3.5f;

            // last 8 channels of f0 row il, from global (L2-hot)
            float4 av0 = __ldg((const float4*)(f0base + il * CD + CF));
            float4 av1 = __ldg((const float4*)(f0base + il * CD + CF + 4));
            float av[8] = {av0.x, av0.y, av0.z, av0.w, av1.x, av1.y, av1.z, av1.w};

            // 3x3 conf_ff patch from raw ff1; scales folded into the exponent
            float p[9];
            int ib = ir >> 3, jb = ir & 7;
            #pragma unroll
            for (int di = 0; di < 3; ++di) {
                int ii = ib + di - 1; ii = (ii < 0) ? ii + 10 : ((ii > 9) ? ii - 10 : ii);
                #pragma unroll
                for (int dj = 0; dj < 3; ++dj) {
                    int jj = jb + dj - 1; jj = (jj < 0) ? jj + 10 : ((jj > 9) ? jj - 10 : jj);
                    int rr = ii * 10 + jj;
                    float s = 0.f;
                    #pragma unroll
                    for (int t = 0; t < 8; ++t)
                        s += av[t] * ff1[rr * 8 + t];
                    p[di * 3 + dj] = s;
                }
            }
            float mx = p[0];
            #pragma unroll
            for (int t = 1; t < 9; ++t) mx = fmaxf(mx, p[t]);
            const float escale = 0.35355339059327373f * 0.1f;
            float h[9], se = 0.f;
            #pragma unroll
            for (int t = 0; t < 9; ++t) { h[t] = __expf((p[t] - mx) * escale); se += h[t]; }
            float inv = 1.f / se;
            float ex = 0.f, ey = 0.f;
            #pragma unroll
            for (int di = 0; di < 3; ++di)
                #pragma unroll
                for (int dj = 0; dj < 3; ++dj) {
                    ex += h[di * 3 + dj] * (float)(dj - 1);
                    ey += h[di * 3 + dj] * (float)(di - 1);
                }
            ex *= inv; ey *= inv;

            float mk0x = mk0[2 * m], mk0y = mk0[2 * m + 1];
            float mk1x = mk1[2 * m], mk1y = mk1[2 * m + 1];
            size_t base = (size_t)MTOT * 4096;
            out[base + 2 * m]     = mk0x + dlx * 2.f;
            out[base + 2 * m + 1] = mk0y + dly * 2.f;
            out[base + 2 * MTOT + 2 * m]     = mk1x + drx * 2.f + ex * 2.f;
            out[base + 2 * MTOT + 2 * m + 1] = mk1y + dry * 2.f + ey * 2.f;
        }
    }
}

extern "C" void kernel_launch(void* const* d_in, const int* in_sizes, int n_in,
                              void* d_out, int out_size)
{
    const float* feat0 = (const float*)d_in[0];
    const float* feat1 = (const float*)d_in[1];
    const float* mk0   = (const float*)d_in[2];
    const float* mk1   = (const float*)d_in[3];
    float* out = (float*)d_out;

    cudaFuncSetAttribute(fine_matching_kernel,
                         cudaFuncAttributeMaxDynamicSharedMemorySize, SMEM_BYTES);
    fine_matching_kernel<<<MTOT, 256, SMEM_BYTES>>>(feat0, feat1, mk0, mk1, out);
}